// round 1
// baseline (speedup 1.0000x reference)
#include <cuda_runtime.h>

// Inputs (metadata order): x0 [N*D f32], x1 [N*D f32], x_c_0, x_c_1 (unused), y [N i32]
// Output: scalar f32 loss.
//
// loss = sum_i [ y_i * ||x0_i - x1_i||^2 + (1-y_i) * max(0, 1.2 - ||x0_i - x1_i||) ] / (2N)
// (everything else in the reference is dead code w.r.t. the returned value)

__global__ void zero_out_kernel(float* out) {
    if (blockIdx.x == 0 && threadIdx.x == 0) out[0] = 0.0f;
}

__global__ __launch_bounds__(256, 8)
void direction_loss_kernel(const float4* __restrict__ x0,
                           const float4* __restrict__ x1,
                           const int* __restrict__ y,
                           float* __restrict__ out,
                           int Dvec,          // D / 4
                           float inv_2N)      // 1 / (2N)
{
    const int row = blockIdx.x;
    const size_t base = (size_t)row * (size_t)Dvec;
    const float4* a = x0 + base;
    const float4* b = x1 + base;

    float s = 0.0f;
    // Dvec = 1024, blockDim = 256 -> 4 iterations per thread, 4 independent
    // float4 loads in flight per thread after unrolling.
    #pragma unroll 4
    for (int i = threadIdx.x; i < Dvec; i += 256) {
        float4 av = a[i];
        float4 bv = b[i];
        float dx = av.x - bv.x;
        float dy = av.y - bv.y;
        float dz = av.z - bv.z;
        float dw = av.w - bv.w;
        s = fmaf(dx, dx, s);
        s = fmaf(dy, dy, s);
        s = fmaf(dz, dz, s);
        s = fmaf(dw, dw, s);
    }

    // Warp reduce
    #pragma unroll
    for (int o = 16; o > 0; o >>= 1)
        s += __shfl_xor_sync(0xffffffffu, s, o);

    __shared__ float wsum[8];
    const int lane = threadIdx.x & 31;
    const int wid  = threadIdx.x >> 5;
    if (lane == 0) wsum[wid] = s;
    __syncthreads();

    if (wid == 0) {
        s = (lane < 8) ? wsum[lane] : 0.0f;
        #pragma unroll
        for (int o = 4; o > 0; o >>= 1)
            s += __shfl_xor_sync(0xffffffffu, s, o);
        if (lane == 0) {
            const float yf = (float)y[row];
            const float e_dist = sqrtf(s);
            const float e_clamped = fmaxf(1.2f - e_dist, 0.0f);
            const float e_loss = yf * s + (1.0f - yf) * e_clamped;
            atomicAdd(out, e_loss * inv_2N);
        }
    }
}

extern "C" void kernel_launch(void* const* d_in, const int* in_sizes, int n_in,
                              void* d_out, int out_size) {
    const float* x0 = (const float*)d_in[0];
    const float* x1 = (const float*)d_in[1];
    const int*   y  = (const int*)d_in[4];
    float* out = (float*)d_out;

    const int N = in_sizes[4];          // 4096
    const int D = in_sizes[0] / N;      // 4096
    const int Dvec = D / 4;             // 1024
    const float inv_2N = 0.5f / (float)N;

    zero_out_kernel<<<1, 32>>>(out);
    direction_loss_kernel<<<N, 256>>>((const float4*)x0, (const float4*)x1,
                                      y, out, Dvec, inv_2N);
}